// round 11
// baseline (speedup 1.0000x reference)
#include <cuda_runtime.h>
#include <math.h>

#define FCOS_INF 1000000000.0f
#define MAXG 64
#define MAXBLK 4096

// Per-block partials: [blk*5 + {cls, box_w, w, center, npos}]
__device__ float g_part[MAXBLK * 5];
__device__ unsigned int g_count;   // zero-init; reset by last block each launch

// Two threads per location: half 0 scans boxes [0, Gh), half 1 scans [Gh, G).
// Box stored as 8 floats: cx, cy, cz, hx, hy, hz, area, label(bits).
template <int GS>  // GS > 0: compile-time G; GS == 0: runtime G
__global__ void __launch_bounds__(256)
fcos_pair_kernel(const float* __restrict__ loc,
                 const float* __restrict__ cls_pred,
                 const float* __restrict__ box_pred,
                 const float* __restrict__ center_pred,
                 const float* __restrict__ bboxes,
                 const int*   __restrict__ gt_labels,
                 const float* __restrict__ spt,
                 const float* __restrict__ soi,
                 float* __restrict__ out,
                 int N, int G_rt) {
    const int G  = (GS > 0) ? GS : G_rt;
    const int Gh = (G + 1) >> 1;

    __shared__ float sbox[MAXG * 8];
    __shared__ float sred[8 * 5];
    __shared__ bool  s_last;

    const int b   = blockIdx.y;
    const int tid = threadIdx.x;

    // Stage boxes as center/halfwidth/area/label
    for (int t = tid; t < G; t += blockDim.x) {
        const float* q = bboxes + ((size_t)b * G + t) * 6;
        const float b0 = q[0], b1 = q[1], b2 = q[2];
        const float b3 = q[3], b4 = q[4], b5 = q[5];
        float* w = sbox + t * 8;
        w[0] = (b0 + b3) * 0.5f;              // cx
        w[1] = (b1 + b4) * 0.5f;              // cy
        w[2] = (b2 + b5) * 0.5f;              // cz
        w[3] = (b3 - b0) * 0.5f;              // hx
        w[4] = (b4 - b1) * 0.5f;              // hy
        w[5] = (b5 - b2) * 0.5f;              // hz
        w[6] = (b3 - b0) * (b4 - b1) * (b5 - b2);   // area
        w[7] = __int_as_float(gt_labels[b * G + t]);
    }
    __syncthreads();

    const int pair  = tid >> 1;          // location within block (0..127)
    const int half  = tid & 1;           // which half of the G range
    const int i     = blockIdx.x * 128 + pair;
    const bool valid = (i < N);

    float x = 0.f, y = 0.f, z = 0.f, s = 1.f, lo = 0.f, hi = 0.f;
    if (valid) {
        x  = loc[i * 3 + 0];
        y  = loc[i * 3 + 1];
        z  = loc[i * 3 + 2];
        s  = spt[i];
        lo = soi[i * 2 + 0];
        hi = soi[i * 2 + 1];
    }

    float best = FCOS_INF;
    int   bg   = -1;

    const int gbeg = half ? Gh : 0;
    const int gend = half ? G  : Gh;

    #pragma unroll 4
    for (int g = gbeg; g < gend; ++g) {
        const float4 v0 = *reinterpret_cast<const float4*>(sbox + g * 8);      // cx,cy,cz,hx
        const float4 v1 = *reinterpret_cast<const float4*>(sbox + g * 8 + 4);  // hy,hz,area,label

        const float dx = x - v0.x, dy = y - v0.y, dz = z - v0.z;
        const float adx = fabsf(dx), ady = fabsf(dy), adz = fabsf(dz);

        // max edge = h + |d|, min edge = h - |d|  (exact identity in reals)
        const float mx = fmaxf(fmaxf(v0.w + adx, v1.x + ady), v1.y + adz);
        const float mn = fminf(fminf(v0.w - adx, v1.x - ady), v1.y - adz);
        const float ma = fmaxf(fmaxf(adx, ady), adz);

        const bool ok = (mn > 0.0f) & (ma < s) & (mx >= lo) & (mx <= hi);
        const float ar = ok ? v1.z : FCOS_INF;
        if (ar < best) { best = ar; bg = g; }   // strict < == first occurrence within half
    }

    // Combine the pair: lower half wins ties (first-occurrence argmin)
    const unsigned fullm = 0xffffffffu;
    const float obest = __shfl_xor_sync(fullm, best, 1);
    const int   obg   = __shfl_xor_sync(fullm, bg,   1);
    float lob, hib; int logi, higi;
    if (half == 0) { lob = best;  logi = bg;  hib = obest; higi = obg; }
    else           { lob = obest; logi = obg; hib = best;  higi = bg;  }
    int wbg = logi;
    if (hib < lob) { wbg = higi; }

    int label = 0;
    float Tl = 1.f, Tt = 1.f, Tf = 1.f, Tr = 1.f, Tb = 1.f, Ta = 1.f;
    if (valid && wbg >= 0) {
        const float4 v0 = *reinterpret_cast<const float4*>(sbox + wbg * 8);
        const float4 v1 = *reinterpret_cast<const float4*>(sbox + wbg * 8 + 4);
        const float dx = x - v0.x, dy = y - v0.y, dz = z - v0.z;
        Tl = dx + v0.w;  Tr = v0.w - dx;
        Tt = dy + v1.x;  Tb = v1.x - dy;
        Tf = dz + v1.y;  Ta = v1.y - dz;
        label = __float_as_int(v1.w);
    }

    float cls_sum = 0.f, box_sum = 0.f, w_sum = 0.f, ctr_sum = 0.f, npos = 0.f;

    // ---- focal loss: each half handles 4 of the 8 classes (coalesced 16B loads) ----
    if (valid) {
        const float4 c4 = *reinterpret_cast<const float4*>(
            cls_pred + ((size_t)b * N + i) * 8 + half * 4);
        const float cl[4] = {c4.x, c4.y, c4.z, c4.w};
        #pragma unroll
        for (int c = 0; c < 4; ++c) {
            const int cg = half * 4 + c;
            const float xl = cl[c];
            const float t  = __expf(-fabsf(xl));
            const float u  = 1.0f + t;
            const float L  = __logf(u);                 // log1p(e^{-|x|})
            const float r  = __fdividef(1.0f, u);
            const float p  = (xl >= 0.0f) ? r : t * r;  // sigmoid(xl)
            const bool posc = (label == cg + 1);
            const float q    = posc ? (1.0f - p) : p;
            const float lin  = posc ? -fminf(xl, 0.0f) : fmaxf(xl, 0.0f);
            const float coef = posc ? 0.25f : 0.75f;
            cls_sum += coef * q * q * (L + lin);
        }
    }

    // ---- box + centerness (positives only, half 0 to avoid double count) ----
    if (valid && half == 0 && label > 0) {
        const float lrmn = fminf(Tl, Tr), lrmx = fmaxf(Tl, Tr);
        const float tbmn = fminf(Tt, Tb), tbmx = fmaxf(Tt, Tb);
        const float fbmn = fminf(Tf, Ta), fbmx = fmaxf(Tf, Ta);
        float cc = __fdividef(lrmn, lrmx) * __fdividef(tbmn, tbmx) * __fdividef(fbmn, fbmx);
        cc = fminf(fmaxf(cc, 1e-8f), 1.0f);
        const float ctr_t = sqrtf(cc);

        const float2 q0 = *reinterpret_cast<const float2*>(box_pred + ((size_t)b * N + i) * 6);
        const float2 q1 = *reinterpret_cast<const float2*>(box_pred + ((size_t)b * N + i) * 6 + 2);
        const float2 q2 = *reinterpret_cast<const float2*>(box_pred + ((size_t)b * N + i) * 6 + 4);
        const float p0 = q0.x, p1 = q0.y, p2 = q1.x;
        const float p3 = q1.y, p4 = q2.x, p5 = q2.y;

        const float pv = (p0 + p3) * (p1 + p4) * (p2 + p5);
        const float tv = (Tl + Tr) * (Tt + Tb) * (Tf + Ta);
        const float inter = (fminf(p0, Tl) + fminf(p3, Tr)) *
                            (fminf(p1, Tt) + fminf(p4, Tb)) *
                            (fminf(p2, Tf) + fminf(p5, Ta));
        const float uni = pv + tv - inter;
        const float iou = __fdividef(inter + 1.0f, uni + 1.0f);
        const float iou_loss = -__logf(fmaxf(iou, 1e-6f));

        box_sum += iou_loss * ctr_t;
        w_sum   += ctr_t;

        const float ct = center_pred[(size_t)b * N + i];
        const float bce = fmaxf(ct, 0.0f) - ct * ctr_t + __logf(1.0f + __expf(-fabsf(ct)));
        ctr_sum += bce;
        npos += 1.0f;
    }

    // ---- block reduce (warp shuffle + smem) ----
    #pragma unroll
    for (int off = 16; off > 0; off >>= 1) {
        cls_sum += __shfl_down_sync(0xffffffffu, cls_sum, off);
        box_sum += __shfl_down_sync(0xffffffffu, box_sum, off);
        w_sum   += __shfl_down_sync(0xffffffffu, w_sum,   off);
        ctr_sum += __shfl_down_sync(0xffffffffu, ctr_sum, off);
        npos    += __shfl_down_sync(0xffffffffu, npos,    off);
    }
    const int lane = tid & 31;
    const int wid  = tid >> 5;
    if (lane == 0) {
        sred[wid * 5 + 0] = cls_sum;
        sred[wid * 5 + 1] = box_sum;
        sred[wid * 5 + 2] = w_sum;
        sred[wid * 5 + 3] = ctr_sum;
        sred[wid * 5 + 4] = npos;
    }
    __syncthreads();

    const int nblk = gridDim.x * gridDim.y;
    const int bid  = blockIdx.y * gridDim.x + blockIdx.x;

    if (tid == 0) {
        float a0 = 0, a1 = 0, a2 = 0, a3 = 0, a4 = 0;
        const int nw = (blockDim.x + 31) >> 5;
        for (int w = 0; w < nw; ++w) {
            a0 += sred[w * 5 + 0];
            a1 += sred[w * 5 + 1];
            a2 += sred[w * 5 + 2];
            a3 += sred[w * 5 + 3];
            a4 += sred[w * 5 + 4];
        }
        g_part[bid * 5 + 0] = a0;
        g_part[bid * 5 + 1] = a1;
        g_part[bid * 5 + 2] = a2;
        g_part[bid * 5 + 3] = a3;
        g_part[bid * 5 + 4] = a4;
        __threadfence();
        const unsigned v = atomicAdd(&g_count, 1u);
        s_last = (v == (unsigned)(nblk - 1));
    }
    __syncthreads();

    // ---- last block: final reduction + output ----
    if (s_last) {
        double a0 = 0, a1 = 0, a2 = 0, a3 = 0, a4 = 0;
        for (int k = tid; k < nblk; k += blockDim.x) {
            a0 += (double)g_part[k * 5 + 0];
            a1 += (double)g_part[k * 5 + 1];
            a2 += (double)g_part[k * 5 + 2];
            a3 += (double)g_part[k * 5 + 3];
            a4 += (double)g_part[k * 5 + 4];
        }
        #pragma unroll
        for (int off = 16; off > 0; off >>= 1) {
            a0 += __shfl_down_sync(0xffffffffu, a0, off);
            a1 += __shfl_down_sync(0xffffffffu, a1, off);
            a2 += __shfl_down_sync(0xffffffffu, a2, off);
            a3 += __shfl_down_sync(0xffffffffu, a3, off);
            a4 += __shfl_down_sync(0xffffffffu, a4, off);
        }
        __shared__ double dred[8 * 5];
        if (lane == 0) {
            dred[wid * 5 + 0] = a0; dred[wid * 5 + 1] = a1; dred[wid * 5 + 2] = a2;
            dred[wid * 5 + 3] = a3; dred[wid * 5 + 4] = a4;
        }
        __syncthreads();
        if (tid == 0) {
            double t0 = 0, t1 = 0, t2 = 0, t3 = 0, t4 = 0;
            const int nw = (blockDim.x + 31) >> 5;
            for (int w = 0; w < nw; ++w) {
                t0 += dred[w * 5 + 0]; t1 += dred[w * 5 + 1]; t2 += dred[w * 5 + 2];
                t3 += dred[w * 5 + 3]; t4 += dred[w * 5 + 4];
            }
            const double B = (double)gridDim.y;
            out[0] = (float)(t0 / (t4 + B));
            out[1] = (float)(t1 / fmax(t2, 1e-8));
            out[2] = (float)(t3 / fmax(t4, 1.0));
            g_count = 0;   // reset for next graph replay
        }
    }
}

extern "C" void kernel_launch(void* const* d_in, const int* in_sizes, int n_in,
                              void* d_out, int out_size) {
    const float* loc         = (const float*)d_in[0];
    const float* cls_pred    = (const float*)d_in[1];
    const float* box_pred    = (const float*)d_in[2];
    const float* center_pred = (const float*)d_in[3];
    const float* bboxes      = (const float*)d_in[4];
    const int*   gt_labels   = (const int*)  d_in[5];
    const float* spt         = (const float*)d_in[7];
    const float* soi         = (const float*)d_in[8];

    const int N = in_sizes[7];
    const int B = in_sizes[3] / N;
    const int G = in_sizes[5] / B;

    dim3 grid((N + 127) / 128, B);   // 2 threads per location, 128 locations/block
    if (G == 48) {
        fcos_pair_kernel<48><<<grid, 256>>>(loc, cls_pred, box_pred, center_pred,
                                            bboxes, gt_labels, spt, soi,
                                            (float*)d_out, N, G);
    } else {
        fcos_pair_kernel<0><<<grid, 256>>>(loc, cls_pred, box_pred, center_pred,
                                           bboxes, gt_labels, spt, soi,
                                           (float*)d_out, N, G);
    }
}

// round 13
// speedup vs baseline: 1.1347x; 1.1347x over previous
#include <cuda_runtime.h>
#include <math.h>

#define FCOS_INF 1000000000.0f
#define MAXG 64
#define MAXBLK 4096

// Per-block partials: [blk*5 + {cls, box_w, w, center, npos}]
__device__ float g_part[MAXBLK * 5];
__device__ unsigned int g_count;   // zero-init; reset by last block each launch

// 2 locations/thread, 512 locations/block. Boxes staged as center/halfwidth,
// then compacted per-block by a level-aware necessary-condition filter.
template <int GS>  // GS > 0: compile-time G; GS == 0: runtime G
__global__ void __launch_bounds__(256)
fcos_filt_kernel(const float* __restrict__ loc,
                 const float* __restrict__ cls_pred,
                 const float* __restrict__ box_pred,
                 const float* __restrict__ center_pred,
                 const float* __restrict__ bboxes,
                 const int*   __restrict__ gt_labels,
                 const float* __restrict__ spt,
                 const float* __restrict__ soi,
                 float* __restrict__ out,
                 int N, int G_rt) {
    const int G = (GS > 0) ? GS : G_rt;

    // 8 floats per box: cx, cy, cz, hx, hy, hz, area, label(bits)
    __shared__ float sbox[MAXG * 8];
    __shared__ float scbox[MAXG * 8];   // compacted candidates (order preserved)
    __shared__ int   skeep[MAXG];
    __shared__ int   sslot[MAXG];
    __shared__ int   sGc;
    __shared__ float sred[8 * 5];
    __shared__ bool  s_last;

    const int b   = blockIdx.y;
    const int tid = threadIdx.x;

    // Block-level union bounds for the prefilter (levels are ordered; soi/spt
    // monotone across the block, but take min/max of endpoints to be safe).
    const int first = min(blockIdx.x * 512, N - 1);
    const int last  = min(blockIdx.x * 512 + 511, N - 1);
    const float lo_blk = fminf(soi[2 * first], soi[2 * last]);
    const float hi_blk = fmaxf(soi[2 * first + 1], soi[2 * last + 1]);
    const float s_blk  = fmaxf(spt[first], spt[last]);

    // Stage boxes + per-box keep flag
    for (int t = tid; t < G; t += blockDim.x) {
        const float* q = bboxes + ((size_t)b * G + t) * 6;
        const float b0 = q[0], b1 = q[1], b2 = q[2];
        const float b3 = q[3], b4 = q[4], b5 = q[5];
        const float hx = (b3 - b0) * 0.5f;
        const float hy = (b4 - b1) * 0.5f;
        const float hz = (b5 - b2) * 0.5f;
        float* w = sbox + t * 8;
        w[0] = (b0 + b3) * 0.5f;
        w[1] = (b1 + b4) * 0.5f;
        w[2] = (b2 + b5) * 0.5f;
        w[3] = hx; w[4] = hy; w[5] = hz;
        w[6] = (b3 - b0) * (b4 - b1) * (b5 - b2);
        w[7] = __int_as_float(gt_labels[b * G + t]);
        const float maxh = fmaxf(fmaxf(hx, hy), hz);
        // necessary condition: maxh <= mx <= hi and mx < maxh + s (since ma < s)
        skeep[t] = (maxh <= hi_blk) & (maxh + s_blk > lo_blk);
    }
    __syncthreads();

    // Serial order-preserving prefix (G <= 64, ~cheap)
    if (tid == 0) {
        int c = 0;
        for (int t = 0; t < G; ++t) {
            sslot[t] = skeep[t] ? c : -1;
            c += skeep[t];
        }
        sGc = c;
    }
    __syncthreads();

    // Parallel compaction copy
    for (int t = tid; t < G; t += blockDim.x) {
        const int sl = sslot[t];
        if (sl >= 0) {
            const float4 a0 = *reinterpret_cast<const float4*>(sbox + t * 8);
            const float4 a1 = *reinterpret_cast<const float4*>(sbox + t * 8 + 4);
            *reinterpret_cast<float4*>(scbox + sl * 8)     = a0;
            *reinterpret_cast<float4*>(scbox + sl * 8 + 4) = a1;
        }
    }
    __syncthreads();

    const int Gc = sGc;

    // Two locations per thread (R10 layout — best measured)
    const int i0 = blockIdx.x * 512 + tid;
    const int i1 = i0 + 256;
    const int idx[2]    = {i0, i1};
    const bool valid[2] = {i0 < N, i1 < N};

    float X[2] = {0.f, 0.f}, Y[2] = {0.f, 0.f}, Z[2] = {0.f, 0.f};
    float S[2] = {1.f, 1.f}, LO[2] = {0.f, 0.f}, HI[2] = {0.f, 0.f};
    #pragma unroll
    for (int j = 0; j < 2; ++j) {
        if (valid[j]) {
            X[j]  = loc[idx[j] * 3 + 0];
            Y[j]  = loc[idx[j] * 3 + 1];
            Z[j]  = loc[idx[j] * 3 + 2];
            S[j]  = spt[idx[j]];
            LO[j] = soi[idx[j] * 2 + 0];
            HI[j] = soi[idx[j] * 2 + 1];
        }
    }

    float best[2] = {FCOS_INF, FCOS_INF};
    int   bg[2]   = {-1, -1};

    #pragma unroll 4
    for (int g = 0; g < Gc; ++g) {
        const float4 v0 = *reinterpret_cast<const float4*>(scbox + g * 8);      // cx,cy,cz,hx
        const float4 v1 = *reinterpret_cast<const float4*>(scbox + g * 8 + 4);  // hy,hz,area,label

        #pragma unroll
        for (int j = 0; j < 2; ++j) {
            const float adx = fabsf(X[j] - v0.x);
            const float ady = fabsf(Y[j] - v0.y);
            const float adz = fabsf(Z[j] - v0.z);

            const float mx = fmaxf(fmaxf(v0.w + adx, v1.x + ady), v1.y + adz);
            const float mn = fminf(fminf(v0.w - adx, v1.x - ady), v1.y - adz);
            const float ma = fmaxf(fmaxf(adx, ady), adz);

            const bool ok = (mn > 0.0f) & (ma < S[j]) & (mx >= LO[j]) & (mx <= HI[j]);
            const float ar = ok ? v1.z : FCOS_INF;
            if (ar < best[j]) { best[j] = ar; bg[j] = g; }   // first-occurrence argmin
        }
    }

    float cls_sum = 0.f, box_sum = 0.f, w_sum = 0.f, ctr_sum = 0.f, npos = 0.f;

    #pragma unroll
    for (int j = 0; j < 2; ++j) {
        if (!valid[j]) continue;
        const int i = idx[j];

        int label = 0;
        float Tl = 1.f, Tt = 1.f, Tf = 1.f, Tr = 1.f, Tb = 1.f, Ta = 1.f;
        if (bg[j] >= 0) {
            const float4 v0 = *reinterpret_cast<const float4*>(scbox + bg[j] * 8);
            const float4 v1 = *reinterpret_cast<const float4*>(scbox + bg[j] * 8 + 4);
            const float dx = X[j] - v0.x, dy = Y[j] - v0.y, dz = Z[j] - v0.z;
            Tl = dx + v0.w;  Tr = v0.w - dx;
            Tt = dy + v1.x;  Tb = v1.x - dy;
            Tf = dz + v1.y;  Ta = v1.y - dz;
            label = __float_as_int(v1.w);
        }

        // ---- focal loss, C=8 classes ----
        const float4 c0 = *reinterpret_cast<const float4*>(cls_pred + ((size_t)b * N + i) * 8);
        const float4 c1 = *reinterpret_cast<const float4*>(cls_pred + ((size_t)b * N + i) * 8 + 4);
        const float cl[8] = {c0.x, c0.y, c0.z, c0.w, c1.x, c1.y, c1.z, c1.w};
        #pragma unroll
        for (int c = 0; c < 8; ++c) {
            const float xl = cl[c];
            const float t  = __expf(-fabsf(xl));
            const float u  = 1.0f + t;
            const float L  = __logf(u);                 // log1p(e^{-|x|})
            const float r  = __fdividef(1.0f, u);
            const float p  = (xl >= 0.0f) ? r : t * r;  // sigmoid(xl)
            const bool posc = (label == c + 1);
            const float q    = posc ? (1.0f - p) : p;
            const float lin  = posc ? -fminf(xl, 0.0f) : fmaxf(xl, 0.0f);
            const float coef = posc ? 0.25f : 0.75f;
            cls_sum += coef * q * q * (L + lin);
        }

        // ---- box + centerness (positives only) ----
        if (label > 0) {
            const float lrmn = fminf(Tl, Tr), lrmx = fmaxf(Tl, Tr);
            const float tbmn = fminf(Tt, Tb), tbmx = fmaxf(Tt, Tb);
            const float fbmn = fminf(Tf, Ta), fbmx = fmaxf(Tf, Ta);
            float cc = __fdividef(lrmn, lrmx) * __fdividef(tbmn, tbmx) * __fdividef(fbmn, fbmx);
            cc = fminf(fmaxf(cc, 1e-8f), 1.0f);
            const float ctr_t = sqrtf(cc);

            const float2 q0 = *reinterpret_cast<const float2*>(box_pred + ((size_t)b * N + i) * 6);
            const float2 q1 = *reinterpret_cast<const float2*>(box_pred + ((size_t)b * N + i) * 6 + 2);
            const float2 q2 = *reinterpret_cast<const float2*>(box_pred + ((size_t)b * N + i) * 6 + 4);
            const float p0 = q0.x, p1 = q0.y, p2 = q1.x;
            const float p3 = q1.y, p4 = q2.x, p5 = q2.y;

            const float pv = (p0 + p3) * (p1 + p4) * (p2 + p5);
            const float tv = (Tl + Tr) * (Tt + Tb) * (Tf + Ta);
            const float inter = (fminf(p0, Tl) + fminf(p3, Tr)) *
                                (fminf(p1, Tt) + fminf(p4, Tb)) *
                                (fminf(p2, Tf) + fminf(p5, Ta));
            const float uni = pv + tv - inter;
            const float iou = __fdividef(inter + 1.0f, uni + 1.0f);
            const float iou_loss = -__logf(fmaxf(iou, 1e-6f));

            box_sum += iou_loss * ctr_t;
            w_sum   += ctr_t;

            const float ct = center_pred[(size_t)b * N + i];
            const float bce = fmaxf(ct, 0.0f) - ct * ctr_t + __logf(1.0f + __expf(-fabsf(ct)));
            ctr_sum += bce;
            npos += 1.0f;
        }
    }

    // ---- block reduce (warp shuffle + smem) ----
    #pragma unroll
    for (int off = 16; off > 0; off >>= 1) {
        cls_sum += __shfl_down_sync(0xffffffffu, cls_sum, off);
        box_sum += __shfl_down_sync(0xffffffffu, box_sum, off);
        w_sum   += __shfl_down_sync(0xffffffffu, w_sum,   off);
        ctr_sum += __shfl_down_sync(0xffffffffu, ctr_sum, off);
        npos    += __shfl_down_sync(0xffffffffu, npos,    off);
    }
    const int lane = tid & 31;
    const int wid  = tid >> 5;
    if (lane == 0) {
        sred[wid * 5 + 0] = cls_sum;
        sred[wid * 5 + 1] = box_sum;
        sred[wid * 5 + 2] = w_sum;
        sred[wid * 5 + 3] = ctr_sum;
        sred[wid * 5 + 4] = npos;
    }
    __syncthreads();

    const int nblk = gridDim.x * gridDim.y;
    const int bid  = blockIdx.y * gridDim.x + blockIdx.x;

    if (tid == 0) {
        float a0 = 0, a1 = 0, a2 = 0, a3 = 0, a4 = 0;
        const int nw = (blockDim.x + 31) >> 5;
        for (int w = 0; w < nw; ++w) {
            a0 += sred[w * 5 + 0];
            a1 += sred[w * 5 + 1];
            a2 += sred[w * 5 + 2];
            a3 += sred[w * 5 + 3];
            a4 += sred[w * 5 + 4];
        }
        g_part[bid * 5 + 0] = a0;
        g_part[bid * 5 + 1] = a1;
        g_part[bid * 5 + 2] = a2;
        g_part[bid * 5 + 3] = a3;
        g_part[bid * 5 + 4] = a4;
        __threadfence();
        const unsigned v = atomicAdd(&g_count, 1u);
        s_last = (v == (unsigned)(nblk - 1));
    }
    __syncthreads();

    // ---- last block: final reduction + output ----
    if (s_last) {
        double a0 = 0, a1 = 0, a2 = 0, a3 = 0, a4 = 0;
        for (int k = tid; k < nblk; k += blockDim.x) {
            a0 += (double)g_part[k * 5 + 0];
            a1 += (double)g_part[k * 5 + 1];
            a2 += (double)g_part[k * 5 + 2];
            a3 += (double)g_part[k * 5 + 3];
            a4 += (double)g_part[k * 5 + 4];
        }
        #pragma unroll
        for (int off = 16; off > 0; off >>= 1) {
            a0 += __shfl_down_sync(0xffffffffu, a0, off);
            a1 += __shfl_down_sync(0xffffffffu, a1, off);
            a2 += __shfl_down_sync(0xffffffffu, a2, off);
            a3 += __shfl_down_sync(0xffffffffu, a3, off);
            a4 += __shfl_down_sync(0xffffffffu, a4, off);
        }
        __shared__ double dred[8 * 5];
        if (lane == 0) {
            dred[wid * 5 + 0] = a0; dred[wid * 5 + 1] = a1; dred[wid * 5 + 2] = a2;
            dred[wid * 5 + 3] = a3; dred[wid * 5 + 4] = a4;
        }
        __syncthreads();
        if (tid == 0) {
            double t0 = 0, t1 = 0, t2 = 0, t3 = 0, t4 = 0;
            const int nw = (blockDim.x + 31) >> 5;
            for (int w = 0; w < nw; ++w) {
                t0 += dred[w * 5 + 0]; t1 += dred[w * 5 + 1]; t2 += dred[w * 5 + 2];
                t3 += dred[w * 5 + 3]; t4 += dred[w * 5 + 4];
            }
            const double B = (double)gridDim.y;
            out[0] = (float)(t0 / (t4 + B));
            out[1] = (float)(t1 / fmax(t2, 1e-8));
            out[2] = (float)(t3 / fmax(t4, 1.0));
            g_count = 0;   // reset for next graph replay
        }
    }
}

extern "C" void kernel_launch(void* const* d_in, const int* in_sizes, int n_in,
                              void* d_out, int out_size) {
    const float* loc         = (const float*)d_in[0];
    const float* cls_pred    = (const float*)d_in[1];
    const float* box_pred    = (const float*)d_in[2];
    const float* center_pred = (const float*)d_in[3];
    const float* bboxes      = (const float*)d_in[4];
    const int*   gt_labels   = (const int*)  d_in[5];
    const float* spt         = (const float*)d_in[7];
    const float* soi         = (const float*)d_in[8];

    const int N = in_sizes[7];
    const int B = in_sizes[3] / N;
    const int G = in_sizes[5] / B;

    dim3 grid((N + 511) / 512, B);   // 512 locations/block, 2 per thread
    if (G == 48) {
        fcos_filt_kernel<48><<<grid, 256>>>(loc, cls_pred, box_pred, center_pred,
                                            bboxes, gt_labels, spt, soi,
                                            (float*)d_out, N, G);
    } else {
        fcos_filt_kernel<0><<<grid, 256>>>(loc, cls_pred, box_pred, center_pred,
                                           bboxes, gt_labels, spt, soi,
                                           (float*)d_out, N, G);
    }
}